// round 13
// baseline (speedup 1.0000x reference)
#include <cuda_runtime.h>
#include <math.h>

// ---------------- problem constants ----------------
#define NB 2048

// output layout: rec | mu | lv | logits | probs
#define OFF_REC  0
#define OFF_MU   (NB*784)
#define OFF_LV   (OFF_MU + NB*64)
#define OFF_LOG  (OFF_LV + NB*64)
#define OFF_PROB (OFF_LOG + NB*8)

// ---------------- scratch (device globals; reused across stages) ----------------
__device__ float g_bufA[(size_t)NB*32*28*28]; // enc h1  /  dec h2 (pre conv3)
__device__ float g_bufB[(size_t)NB*64*14*14]; // enc h2  /  dec h1 (pre conv2)
__device__ float g_bufC[(size_t)NB*128*7*7];  // enc h3(flat 6272) / dec fc out (1568)
__device__ float g_mu[NB*64];
__device__ float g_lv[NB*64];
__device__ float g_z[NB*64];
__device__ int   g_expert[NB];

__device__ __forceinline__ float eluf(float v)     { return v > 0.f ? v : expm1f(v); }
__device__ __forceinline__ float sigmoidf_(float v){ return 1.f / (1.f + expf(-v)); }

// ===== enc conv1 tiled: 1x28x28 -> 32x28x28, relu. block/image, 256 thr =====
__global__ void __launch_bounds__(256) t_enc1(const float* __restrict__ x,
                                              const float* __restrict__ W,
                                              const float* __restrict__ B) {
    int b = blockIdx.x;
    __shared__ float sIn[784];
    const float* in = x + (size_t)b * 784;
    for (int i = threadIdx.x; i < 784; i += 256) sIn[i] = in[i];
    __syncthreads();
    float* out = g_bufA + (size_t)b * 25088;
    for (int t = threadIdx.x; t < 32 * 28; t += 256) {
        int oc = t / 28, y = t % 28;
        float bi = __ldg(&B[oc]);
        float acc[28];
#pragma unroll
        for (int i = 0; i < 28; i++) acc[i] = bi;
#pragma unroll
        for (int ky = 0; ky < 3; ky++) {
            int iy = y + ky - 1;
            if (iy < 0 || iy > 27) continue;
            const float* row = sIn + iy * 28;
            float r[28];
#pragma unroll
            for (int j = 0; j < 28; j++) r[j] = row[j];
#pragma unroll
            for (int kx = 0; kx < 3; kx++) {
                float w = __ldg(&W[(oc * 3 + ky) * 3 + kx]);
#pragma unroll
                for (int xx = 0; xx < 28; xx++) {
                    int ix = xx + kx - 1;
                    if (ix >= 0 && ix < 28) acc[xx] = fmaf(r[ix], w, acc[xx]);
                }
            }
        }
#pragma unroll
        for (int xx = 0; xx < 28; xx++) out[oc * 784 + y * 28 + xx] = fmaxf(acc[xx], 0.f);
    }
}

// ===== enc conv2 tiled: 32x28x28 -> 64x14x14 (s2,p1), relu =====
__global__ void __launch_bounds__(448) t_enc2(const float* __restrict__ W,
                                              const float* __restrict__ B) {
    __shared__ float sIn[8 * 784];
    int b = blockIdx.x;
    int tid = threadIdx.x;
    int ocp = tid / 14, y = tid % 14;
    int oc0 = ocp * 2, oc1 = oc0 + 1;
    float a0[14], a1[14];
    float b0 = __ldg(&B[oc0]), b1 = __ldg(&B[oc1]);
#pragma unroll
    for (int i = 0; i < 14; i++) { a0[i] = b0; a1[i] = b1; }
    const float* in = g_bufA + (size_t)b * 25088;
    for (int tt = 0; tt < 4; tt++) {
        int ic0 = tt * 8;
        __syncthreads();
        for (int i = tid; i < 6272; i += 448) sIn[i] = in[ic0 * 784 + i];
        __syncthreads();
#pragma unroll
        for (int ic = 0; ic < 8; ic++) {
            const float* base = sIn + ic * 784;
            const float* w0 = W + ((size_t)oc0 * 32 + ic0 + ic) * 9;
            const float* w1 = W + ((size_t)oc1 * 32 + ic0 + ic) * 9;
#pragma unroll
            for (int ky = 0; ky < 3; ky++) {
                int iy = 2 * y + ky - 1;
                if (iy < 0 || iy > 27) continue;
                const float* row = base + iy * 28;
                float r[28];
#pragma unroll
                for (int j = 0; j < 28; j++) r[j] = row[j];
#pragma unroll
                for (int kx = 0; kx < 3; kx++) {
                    float wa = __ldg(&w0[ky * 3 + kx]);
                    float wb = __ldg(&w1[ky * 3 + kx]);
#pragma unroll
                    for (int xx = 0; xx < 14; xx++) {
                        int ix = 2 * xx + kx - 1;
                        if (ix >= 0 && ix < 28) {
                            a0[xx] = fmaf(r[ix], wa, a0[xx]);
                            a1[xx] = fmaf(r[ix], wb, a1[xx]);
                        }
                    }
                }
            }
        }
    }
    float* out = g_bufB + (size_t)b * 12544;
#pragma unroll
    for (int xx = 0; xx < 14; xx++) {
        out[oc0 * 196 + y * 14 + xx] = fmaxf(a0[xx], 0.f);
        out[oc1 * 196 + y * 14 + xx] = fmaxf(a1[xx], 0.f);
    }
}

// ===== enc conv3 tiled: 64x14x14 -> 128x7x7 (s2,p1), relu =====
__global__ void __launch_bounds__(448) t_enc3(const float* __restrict__ W,
                                              const float* __restrict__ B) {
    __shared__ float sIn[32 * 196];
    int b = blockIdx.x;
    int tid = threadIdx.x;
    int ocp = tid / 7, y = tid % 7;
    int oc0 = ocp * 2, oc1 = oc0 + 1;
    float a0[7], a1[7];
    float b0 = __ldg(&B[oc0]), b1 = __ldg(&B[oc1]);
#pragma unroll
    for (int i = 0; i < 7; i++) { a0[i] = b0; a1[i] = b1; }
    const float* in = g_bufB + (size_t)b * 12544;
    for (int tt = 0; tt < 2; tt++) {
        int ic0 = tt * 32;
        __syncthreads();
        for (int i = tid; i < 6272; i += 448) sIn[i] = in[ic0 * 196 + i];
        __syncthreads();
#pragma unroll
        for (int ic = 0; ic < 32; ic++) {
            const float* base = sIn + ic * 196;
            const float* w0 = W + ((size_t)oc0 * 64 + ic0 + ic) * 9;
            const float* w1 = W + ((size_t)oc1 * 64 + ic0 + ic) * 9;
#pragma unroll
            for (int ky = 0; ky < 3; ky++) {
                int iy = 2 * y + ky - 1;
                if (iy < 0 || iy > 13) continue;
                const float* row = base + iy * 14;
                float r[14];
#pragma unroll
                for (int j = 0; j < 14; j++) r[j] = row[j];
#pragma unroll
                for (int kx = 0; kx < 3; kx++) {
                    float wa = __ldg(&w0[ky * 3 + kx]);
                    float wb = __ldg(&w1[ky * 3 + kx]);
#pragma unroll
                    for (int xx = 0; xx < 7; xx++) {
                        int ix = 2 * xx + kx - 1;
                        if (ix >= 0 && ix < 14) {
                            a0[xx] = fmaf(r[ix], wa, a0[xx]);
                            a1[xx] = fmaf(r[ix], wb, a1[xx]);
                        }
                    }
                }
            }
        }
    }
    float* out = g_bufC + (size_t)b * 6272;
#pragma unroll
    for (int xx = 0; xx < 7; xx++) {
        out[oc0 * 49 + y * 7 + xx] = fmaxf(a0[xx], 0.f);
        out[oc1 * 49 + y * 7 + xx] = fmaxf(a1[xx], 0.f);
    }
}

// ===== fc mu/lv v2: both operands staged in smem, float4 broadcast A reads =====
// grid 128 x 256 thr; 16 samples/block; j = tid&127 selects output (mu j / lv j-64).
#define FC_PAD 20  // sA row stride in floats (16 rows + pad, 16B-aligned)
__global__ void __launch_bounds__(256) t_fc2(const float* __restrict__ Wmu,
                                             const float* __restrict__ bmu,
                                             const float* __restrict__ Wlv,
                                             const float* __restrict__ blv,
                                             float* __restrict__ out) {
    __shared__ float sA[64 * FC_PAD];   // [kk][row(16)+pad]
    __shared__ float sW[64 * 128];      // [kk][j]
    int blk = blockIdx.x;
    int tid = threadIdx.x;
    int j  = tid & 127;
    int rg = tid >> 7; // 0/1 -> rows rg*8..rg*8+7
    float bi = (j < 64) ? __ldg(&bmu[j]) : __ldg(&blv[j - 64]);
    float acc[8];
#pragma unroll
    for (int r = 0; r < 8; r++) acc[r] = bi;
    for (int k0 = 0; k0 < 6272; k0 += 64) {
        __syncthreads();
        // A tile: 16 rows x 64 k (kk-major with pad)
        for (int i = tid; i < 1024; i += 256) {
            int kk = i & 63, row = i >> 6;
            sA[kk * FC_PAD + row] = g_bufC[(size_t)(blk * 16 + row) * 6272 + k0 + kk];
        }
        // W tile: 64 k x 128 j (mu | lv)
        for (int i = tid; i < 8192; i += 256) {
            int jj = i & 127, kk = i >> 7;
            sW[i] = (jj < 64) ? __ldg(&Wmu[(size_t)(k0 + kk) * 64 + jj])
                              : __ldg(&Wlv[(size_t)(k0 + kk) * 64 + jj - 64]);
        }
        __syncthreads();
#pragma unroll 16
        for (int kk = 0; kk < 64; kk++) {
            float w = sW[kk * 128 + j];
            float4 aa = *(const float4*)&sA[kk * FC_PAD + rg * 8];
            float4 ab = *(const float4*)&sA[kk * FC_PAD + rg * 8 + 4];
            acc[0] = fmaf(aa.x, w, acc[0]);
            acc[1] = fmaf(aa.y, w, acc[1]);
            acc[2] = fmaf(aa.z, w, acc[2]);
            acc[3] = fmaf(aa.w, w, acc[3]);
            acc[4] = fmaf(ab.x, w, acc[4]);
            acc[5] = fmaf(ab.y, w, acc[5]);
            acc[6] = fmaf(ab.z, w, acc[6]);
            acc[7] = fmaf(ab.w, w, acc[7]);
        }
    }
#pragma unroll
    for (int r = 0; r < 8; r++) {
        int b = blk * 16 + rg * 8 + r;
        if (j < 64) { g_mu[b * 64 + j] = acc[r];        out[OFF_MU + b * 64 + j] = acc[r]; }
        else        { g_lv[b * 64 + j - 64] = acc[r];   out[OFF_LV + b * 64 + j - 64] = acc[r]; }
    }
}

// ===== reparam + gating + softmax + argmax (verified) =====
__global__ void __launch_bounds__(256) n_gate(const float* __restrict__ eps,
                                              const float* __restrict__ W1, const float* __restrict__ B1,
                                              const float* __restrict__ W2, const float* __restrict__ B2,
                                              const float* __restrict__ W3, const float* __restrict__ B3,
                                              float* __restrict__ out) {
    __shared__ float sW1[4096], sW2[2048], sW3[256], sB1[64], sB2[32], sB3[8];
    int tid = threadIdx.x;
    for (int i = tid; i < 4096; i += 256) sW1[i] = W1[i];
    for (int i = tid; i < 2048; i += 256) sW2[i] = W2[i];
    sW3[tid] = W3[tid];
    if (tid < 64) sB1[tid] = B1[tid];
    if (tid < 32) sB2[tid] = B2[tid];
    if (tid < 8)  sB3[tid] = B3[tid];
    __syncthreads();
    int b = blockIdx.x * 256 + tid;
    float z[64];
#pragma unroll 8
    for (int k = 0; k < 64; k++)
        z[k] = g_mu[b * 64 + k] + __ldg(&eps[b * 64 + k]) * expf(0.5f * g_lv[b * 64 + k]);
    for (int k = 0; k < 64; k++) g_z[b * 64 + k] = z[k];

    float a1[64];
    for (int j = 0; j < 64; j++) {
        float a = sB1[j];
#pragma unroll 8
        for (int k = 0; k < 64; k++) a = fmaf(z[k], sW1[k * 64 + j], a);
        a1[j] = fmaxf(a, 0.f);
    }
    float a2[32];
    for (int j = 0; j < 32; j++) {
        float a = sB2[j];
#pragma unroll 8
        for (int k = 0; k < 64; k++) a = fmaf(a1[k], sW2[k * 32 + j], a);
        a2[j] = fmaxf(a, 0.f);
    }
    float a3[8];
#pragma unroll
    for (int j = 0; j < 8; j++) {
        float a = sB3[j];
#pragma unroll
        for (int k = 0; k < 32; k++) a = fmaf(a2[k], sW3[k * 8 + j], a);
        a3[j] = a;
    }
    float m = a3[0];
#pragma unroll
    for (int e = 1; e < 8; e++) m = fmaxf(m, a3[e]);
    float p[8], s = 0.f;
#pragma unroll
    for (int e = 0; e < 8; e++) { p[e] = expf(a3[e] - m); s += p[e]; }
    float inv = 1.f / s;
    int best = 0; float bv = -1e30f;
#pragma unroll
    for (int e = 0; e < 8; e++) {
        float pe = p[e] * inv;
        out[OFF_PROB + b * 8 + e] = pe;
        out[OFF_LOG + b * 8 + e]  = logf(pe + 1e-8f);
        if (pe > bv) { bv = pe; best = e; }
    }
    g_expert[b] = best;
}

// ===== dec fc (naive, verified): z[64] @ W[e][64,1568] =====
__global__ void __launch_bounds__(256) n_dfc(const float* __restrict__ Wfc,
                                             const float* __restrict__ bfc) {
    int idx = blockIdx.x * 256 + threadIdx.x;
    int j = idx % 1568;
    int b = idx / 1568;
    int e = g_expert[b];
    const float* W = Wfc + (size_t)e * 100352;
    float acc = __ldg(&bfc[(size_t)e * 1568 + j]);
#pragma unroll 8
    for (int k = 0; k < 64; k++)
        acc = fmaf(g_z[b * 64 + k], __ldg(&W[k * 1568 + j]), acc);
    g_bufC[(size_t)b * 1568 + j] = acc;
}

// ===== dec conv1 PHASE-COLLAPSED: up2(32x7x7)->conv3x3 == 2x2 taps on 7x7 =====
__global__ void __launch_bounds__(448) p_dec1(const float* __restrict__ Wall,
                                              const float* __restrict__ ball) {
    __shared__ float sIn[1568];
    int b = blockIdx.x;
    int tid = threadIdx.x;
    int e = g_expert[b];
    const float* in = g_bufC + (size_t)b * 1568;
    for (int i = tid; i < 1568; i += 448) sIn[i] = in[i];
    __syncthreads();
    int ocp = tid / 14, y = tid % 14;
    int oc0 = ocp * 2, oc1 = oc0 + 1;
    int dy = y & 1, i = y >> 1;
    const float* W = Wall + (size_t)e * 18432;
    float a0[14], a1[14];
    float bb0 = __ldg(&ball[e * 64 + oc0]), bb1 = __ldg(&ball[e * 64 + oc1]);
#pragma unroll
    for (int k = 0; k < 14; k++) { a0[k] = bb0; a1[k] = bb1; }
    int r0 = dy ? i : i - 1;
    int r1 = dy ? i + 1 : i;
    bool t0ok = (r0 >= 0);
    bool t1ok = (r1 <= 6);
#pragma unroll 2
    for (int ic = 0; ic < 32; ic++) {
        const float* base = sIn + ic * 49;
        const float* wv0 = W + ((size_t)oc0 * 32 + ic) * 9;
        const float* wv1 = W + ((size_t)oc1 * 32 + ic) * 9;
        float p00 = __ldg(&wv0[0]), p01 = __ldg(&wv0[1]), p02 = __ldg(&wv0[2]);
        float p10 = __ldg(&wv0[3]), p11 = __ldg(&wv0[4]), p12 = __ldg(&wv0[5]);
        float p20 = __ldg(&wv0[6]), p21 = __ldg(&wv0[7]), p22 = __ldg(&wv0[8]);
        float q00 = __ldg(&wv1[0]), q01 = __ldg(&wv1[1]), q02 = __ldg(&wv1[2]);
        float q10 = __ldg(&wv1[3]), q11 = __ldg(&wv1[4]), q12 = __ldg(&wv1[5]);
        float q20 = __ldg(&wv1[6]), q21 = __ldg(&wv1[7]), q22 = __ldg(&wv1[8]);
        float u0p = dy ? (p00 + p10) : p00, u1p = dy ? (p01 + p11) : p01, u2p = dy ? (p02 + p12) : p02;
        float v0p = dy ? p20 : (p10 + p20), v1p = dy ? p21 : (p11 + p21), v2p = dy ? p22 : (p12 + p22);
        float u0q = dy ? (q00 + q10) : q00, u1q = dy ? (q01 + q11) : q01, u2q = dy ? (q02 + q12) : q02;
        float v0q = dy ? q20 : (q10 + q20), v1q = dy ? q21 : (q11 + q21), v2q = dy ? q22 : (q12 + q22);
        if (t0ok) {
            const float* row = base + r0 * 7;
            float r[7];
#pragma unroll
            for (int k = 0; k < 7; k++) r[k] = row[k];
            float Ap = u0p, Bp = u1p + u2p, Cp = u0p + u1p, Dp = u2p;
            float Aq = u0q, Bq = u1q + u2q, Cq = u0q + u1q, Dq = u2q;
#pragma unroll
            for (int jj = 0; jj < 7; jj++) {
                if (jj > 0) { a0[2 * jj] = fmaf(r[jj - 1], Ap, a0[2 * jj]); a1[2 * jj] = fmaf(r[jj - 1], Aq, a1[2 * jj]); }
                a0[2 * jj]     = fmaf(r[jj], Bp, a0[2 * jj]);     a1[2 * jj]     = fmaf(r[jj], Bq, a1[2 * jj]);
                a0[2 * jj + 1] = fmaf(r[jj], Cp, a0[2 * jj + 1]); a1[2 * jj + 1] = fmaf(r[jj], Cq, a1[2 * jj + 1]);
                if (jj < 6) { a0[2 * jj + 1] = fmaf(r[jj + 1], Dp, a0[2 * jj + 1]); a1[2 * jj + 1] = fmaf(r[jj + 1], Dq, a1[2 * jj + 1]); }
            }
        }
        if (t1ok) {
            const float* row = base + r1 * 7;
            float r[7];
#pragma unroll
            for (int k = 0; k < 7; k++) r[k] = row[k];
            float Ap = v0p, Bp = v1p + v2p, Cp = v0p + v1p, Dp = v2p;
            float Aq = v0q, Bq = v1q + v2q, Cq = v0q + v1q, Dq = v2q;
#pragma unroll
            for (int jj = 0; jj < 7; jj++) {
                if (jj > 0) { a0[2 * jj] = fmaf(r[jj - 1], Ap, a0[2 * jj]); a1[2 * jj] = fmaf(r[jj - 1], Aq, a1[2 * jj]); }
                a0[2 * jj]     = fmaf(r[jj], Bp, a0[2 * jj]);     a1[2 * jj]     = fmaf(r[jj], Bq, a1[2 * jj]);
                a0[2 * jj + 1] = fmaf(r[jj], Cp, a0[2 * jj + 1]); a1[2 * jj + 1] = fmaf(r[jj], Cq, a1[2 * jj + 1]);
                if (jj < 6) { a0[2 * jj + 1] = fmaf(r[jj + 1], Dp, a0[2 * jj + 1]); a1[2 * jj + 1] = fmaf(r[jj + 1], Dq, a1[2 * jj + 1]); }
            }
        }
    }
    float* out = g_bufB + (size_t)b * 12544;
#pragma unroll
    for (int xx = 0; xx < 14; xx++) {
        out[oc0 * 196 + y * 14 + xx] = eluf(a0[xx]);
        out[oc1 * 196 + y * 14 + xx] = eluf(a1[xx]);
    }
}

// ===== dec conv2 PHASE-COLLAPSED, 2 oc/thread: up2(64x14x14)->conv == 2x2 taps =====
// block = 448 threads: ocp in [0,16) (2 oc each), y in [0,28).
__global__ void __launch_bounds__(448) p_dec2b(const float* __restrict__ Wall,
                                               const float* __restrict__ ball) {
    __shared__ float sIn[32 * 196];
    int b = blockIdx.x;
    int tid = threadIdx.x;
    int e = g_expert[b];
    int ocp = tid / 28, y = tid % 28;
    int oc0 = ocp * 2, oc1 = oc0 + 1;
    int dy = y & 1, i = y >> 1;
    const float* W = Wall + (size_t)e * 18432;
    const float* in = g_bufB + (size_t)b * 12544;
    float a0[28], a1[28];
    float bb0 = __ldg(&ball[e * 32 + oc0]), bb1 = __ldg(&ball[e * 32 + oc1]);
#pragma unroll
    for (int k = 0; k < 28; k++) { a0[k] = bb0; a1[k] = bb1; }
    int r0 = dy ? i : i - 1;
    int r1 = dy ? i + 1 : i;
    bool t0ok = (r0 >= 0);
    bool t1ok = (r1 <= 13);
    for (int tt = 0; tt < 2; tt++) {
        int ic0 = tt * 32;
        __syncthreads();
        for (int k = tid; k < 6272; k += 448) sIn[k] = in[ic0 * 196 + k];
        __syncthreads();
#pragma unroll 2
        for (int ic = 0; ic < 32; ic++) {
            const float* base = sIn + ic * 196;
            const float* wv0 = W + ((size_t)oc0 * 64 + ic0 + ic) * 9;
            const float* wv1 = W + ((size_t)oc1 * 64 + ic0 + ic) * 9;
            float p00 = __ldg(&wv0[0]), p01 = __ldg(&wv0[1]), p02 = __ldg(&wv0[2]);
            float p10 = __ldg(&wv0[3]), p11 = __ldg(&wv0[4]), p12 = __ldg(&wv0[5]);
            float p20 = __ldg(&wv0[6]), p21 = __ldg(&wv0[7]), p22 = __ldg(&wv0[8]);
            float q00 = __ldg(&wv1[0]), q01 = __ldg(&wv1[1]), q02 = __ldg(&wv1[2]);
            float q10 = __ldg(&wv1[3]), q11 = __ldg(&wv1[4]), q12 = __ldg(&wv1[5]);
            float q20 = __ldg(&wv1[6]), q21 = __ldg(&wv1[7]), q22 = __ldg(&wv1[8]);
            float u0p = dy ? (p00 + p10) : p00, u1p = dy ? (p01 + p11) : p01, u2p = dy ? (p02 + p12) : p02;
            float v0p = dy ? p20 : (p10 + p20), v1p = dy ? p21 : (p11 + p21), v2p = dy ? p22 : (p12 + p22);
            float u0q = dy ? (q00 + q10) : q00, u1q = dy ? (q01 + q11) : q01, u2q = dy ? (q02 + q12) : q02;
            float v0q = dy ? q20 : (q10 + q20), v1q = dy ? q21 : (q11 + q21), v2q = dy ? q22 : (q12 + q22);
            if (t0ok) {
                const float* row = base + r0 * 14;
                float r[14];
#pragma unroll
                for (int k = 0; k < 14; k++) r[k] = row[k];
                float Ap = u0p, Bp = u1p + u2p, Cp = u0p + u1p, Dp = u2p;
                float Aq = u0q, Bq = u1q + u2q, Cq = u0q + u1q, Dq = u2q;
#pragma unroll
                for (int jj = 0; jj < 14; jj++) {
                    if (jj > 0) { a0[2 * jj] = fmaf(r[jj - 1], Ap, a0[2 * jj]); a1[2 * jj] = fmaf(r[jj - 1], Aq, a1[2 * jj]); }
                    a0[2 * jj]     = fmaf(r[jj], Bp, a0[2 * jj]);     a1[2 * jj]     = fmaf(r[jj], Bq, a1[2 * jj]);
                    a0[2 * jj + 1] = fmaf(r[jj], Cp, a0[2 * jj + 1]); a1[2 * jj + 1] = fmaf(r[jj], Cq, a1[2 * jj + 1]);
                    if (jj < 13) { a0[2 * jj + 1] = fmaf(r[jj + 1], Dp, a0[2 * jj + 1]); a1[2 * jj + 1] = fmaf(r[jj + 1], Dq, a1[2 * jj + 1]); }
                }
            }
            if (t1ok) {
                const float* row = base + r1 * 14;
                float r[14];
#pragma unroll
                for (int k = 0; k < 14; k++) r[k] = row[k];
                float Ap = v0p, Bp = v1p + v2p, Cp = v0p + v1p, Dp = v2p;
                float Aq = v0q, Bq = v1q + v2q, Cq = v0q + v1q, Dq = v2q;
#pragma unroll
                for (int jj = 0; jj < 14; jj++) {
                    if (jj > 0) { a0[2 * jj] = fmaf(r[jj - 1], Ap, a0[2 * jj]); a1[2 * jj] = fmaf(r[jj - 1], Aq, a1[2 * jj]); }
                    a0[2 * jj]     = fmaf(r[jj], Bp, a0[2 * jj]);     a1[2 * jj]     = fmaf(r[jj], Bq, a1[2 * jj]);
                    a0[2 * jj + 1] = fmaf(r[jj], Cp, a0[2 * jj + 1]); a1[2 * jj + 1] = fmaf(r[jj], Cq, a1[2 * jj + 1]);
                    if (jj < 13) { a0[2 * jj + 1] = fmaf(r[jj + 1], Dp, a0[2 * jj + 1]); a1[2 * jj + 1] = fmaf(r[jj + 1], Dq, a1[2 * jj + 1]); }
                }
            }
        }
    }
    float* out = g_bufA + (size_t)b * 25088;
#pragma unroll
    for (int xx = 0; xx < 28; xx++) {
        out[oc0 * 784 + y * 28 + xx] = eluf(a0[xx]);
        out[oc1 * 784 + y * 28 + xx] = eluf(a1[xx]);
    }
}

// ===== dec conv3 tiled: 32x28x28 -> 1x28x28, sigmoid -> d_out =====
__global__ void __launch_bounds__(784) t_dec3(const float* __restrict__ Wall,
                                              const float* __restrict__ ball,
                                              float* __restrict__ out) {
    __shared__ float sIn[8 * 784];
    int b = blockIdx.x;
    int tid = threadIdx.x;
    int e = g_expert[b];
    int y = tid / 28, xx = tid % 28;
    const float* W = Wall + (size_t)e * 288;
    const float* in = g_bufA + (size_t)b * 25088;
    float acc = __ldg(&ball[e]);
    for (int tt = 0; tt < 4; tt++) {
        int ic0 = tt * 8;
        __syncthreads();
        for (int i = tid; i < 6272; i += 784) sIn[i] = in[ic0 * 784 + i];
        __syncthreads();
#pragma unroll
        for (int ic = 0; ic < 8; ic++) {
            const float* base = sIn + ic * 784;
            const float* wv = W + (ic0 + ic) * 9;
#pragma unroll
            for (int ky = 0; ky < 3; ky++) {
                int iy = y + ky - 1;
                if (iy < 0 || iy > 27) continue;
#pragma unroll
                for (int kx = 0; kx < 3; kx++) {
                    int ix = xx + kx - 1;
                    if (ix < 0 || ix > 27) continue;
                    acc = fmaf(base[iy * 28 + ix], __ldg(&wv[ky * 3 + kx]), acc);
                }
            }
        }
    }
    out[OFF_REC + b * 784 + tid] = sigmoidf_(acc);
}

// ---------------- launcher ----------------
extern "C" void kernel_launch(void* const* d_in, const int* in_sizes, int n_in,
                              void* d_out, int out_size) {
    // Input-order auto-detection (verified working).
    static const int SZ_INS[26] = {
        1605632, 131072, 288, 32, 18432, 64, 73728, 128,
        401408, 64, 401408, 64, 4096, 64, 2048, 32, 256, 8,
        802816, 12544, 147456, 512, 147456, 256, 2304, 8};
    static const int A[26] = {11, 9, 21, 23, 25, 19, 18, 20, 22, 24, 3, 5, 7,
                              2, 4, 6, 1, 13, 15, 17, 12, 14, 16, 10, 8, 0};
    int perm[26];
    bool ins_ok = (n_in >= 26);
    if (ins_ok) for (int i = 0; i < 26; i++) if (in_sizes[i] != SZ_INS[i]) { ins_ok = false; break; }
    if (ins_ok) {
        for (int i = 0; i < 26; i++) perm[i] = i;
    } else {
        bool alpha_ok = (n_in >= 26);
        if (alpha_ok) for (int k = 0; k < 26; k++) if (in_sizes[k] != SZ_INS[A[k]]) { alpha_ok = false; break; }
        if (alpha_ok) { for (int k = 0; k < 26; k++) perm[A[k]] = k; }
        else          { for (int i = 0; i < 26; i++) perm[i] = i; }
    }
    const float* P[26];
    for (int i = 0; i < 26; i++) P[i] = (const float*)d_in[perm[i]];

    const float* x      = P[0];
    const float* eps    = P[1];
    const float* enc_w1 = P[2];
    const float* enc_b1 = P[3];
    const float* enc_w2 = P[4];
    const float* enc_b2 = P[5];
    const float* enc_w3 = P[6];
    const float* enc_b3 = P[7];
    const float* w_mu   = P[8];
    const float* b_mu   = P[9];
    const float* w_lv   = P[10];
    const float* b_lv   = P[11];
    const float* g_w1   = P[12];
    const float* g_b1   = P[13];
    const float* g_w2   = P[14];
    const float* g_b2   = P[15];
    const float* g_w3   = P[16];
    const float* g_b3   = P[17];
    const float* d_fc_w = P[18];
    const float* d_fc_b = P[19];
    const float* d_w1   = P[20];
    const float* d_b1   = P[21];
    const float* d_w2   = P[22];
    const float* d_b2   = P[23];
    const float* d_w3   = P[24];
    const float* d_b3   = P[25];
    float* out = (float*)d_out;

    t_enc1<<<2048, 256>>>(x, enc_w1, enc_b1);
    t_enc2<<<2048, 448>>>(enc_w2, enc_b2);
    t_enc3<<<2048, 448>>>(enc_w3, enc_b3);
    t_fc2 <<<128, 256>>>(w_mu, b_mu, w_lv, b_lv, out);
    n_gate<<<2048 / 256, 256>>>(eps, g_w1, g_b1, g_w2, g_b2, g_w3, g_b3, out);
    n_dfc <<<2048 * 1568 / 256, 256>>>(d_fc_w, d_fc_b);
    p_dec1<<<2048, 448>>>(d_w1, d_b1);
    p_dec2b<<<2048, 448>>>(d_w2, d_b2);
    t_dec3<<<2048, 784>>>(d_w3, d_b3, out);
}

// round 14
// speedup vs baseline: 1.9986x; 1.9986x over previous
#include <cuda_runtime.h>
#include <math.h>

// ---------------- problem constants ----------------
#define NB 2048

// output layout: rec | mu | lv | logits | probs
#define OFF_REC  0
#define OFF_MU   (NB*784)
#define OFF_LV   (OFF_MU + NB*64)
#define OFF_LOG  (OFF_LV + NB*64)
#define OFF_PROB (OFF_LOG + NB*8)

// ---------------- scratch (device globals; reused across stages) ----------------
__device__ float g_bufA[(size_t)NB*32*28*28]; // enc h1  /  dec h2 (pre conv3)
__device__ float g_bufB[(size_t)NB*64*14*14]; // enc h2  /  dec h1 (pre conv2)
__device__ float g_bufC[(size_t)NB*128*7*7];  // enc h3(flat 6272) / dec fc out (1568)
__device__ float g_part[4 * NB * 128];        // fc split-K partials [ks][b][j]
__device__ float g_mu[NB*64];
__device__ float g_lv[NB*64];
__device__ float g_z[NB*64];
__device__ int   g_expert[NB];

__device__ __forceinline__ float eluf(float v)     { return v > 0.f ? v : expm1f(v); }
__device__ __forceinline__ float sigmoidf_(float v){ return 1.f / (1.f + expf(-v)); }

// ===== enc conv1 tiled: 1x28x28 -> 32x28x28, relu. block/image, 256 thr =====
__global__ void __launch_bounds__(256) t_enc1(const float* __restrict__ x,
                                              const float* __restrict__ W,
                                              const float* __restrict__ B) {
    int b = blockIdx.x;
    __shared__ float sIn[784];
    const float* in = x + (size_t)b * 784;
    for (int i = threadIdx.x; i < 784; i += 256) sIn[i] = in[i];
    __syncthreads();
    float* out = g_bufA + (size_t)b * 25088;
    for (int t = threadIdx.x; t < 32 * 28; t += 256) {
        int oc = t / 28, y = t % 28;
        float bi = __ldg(&B[oc]);
        float acc[28];
#pragma unroll
        for (int i = 0; i < 28; i++) acc[i] = bi;
#pragma unroll
        for (int ky = 0; ky < 3; ky++) {
            int iy = y + ky - 1;
            if (iy < 0 || iy > 27) continue;
            const float* row = sIn + iy * 28;
            float r[28];
#pragma unroll
            for (int j = 0; j < 28; j++) r[j] = row[j];
#pragma unroll
            for (int kx = 0; kx < 3; kx++) {
                float w = __ldg(&W[(oc * 3 + ky) * 3 + kx]);
#pragma unroll
                for (int xx = 0; xx < 28; xx++) {
                    int ix = xx + kx - 1;
                    if (ix >= 0 && ix < 28) acc[xx] = fmaf(r[ix], w, acc[xx]);
                }
            }
        }
#pragma unroll
        for (int xx = 0; xx < 28; xx++) out[oc * 784 + y * 28 + xx] = fmaxf(acc[xx], 0.f);
    }
}

// ===== enc conv2 tiled: 32x28x28 -> 64x14x14 (s2,p1), relu =====
__global__ void __launch_bounds__(448) t_enc2(const float* __restrict__ W,
                                              const float* __restrict__ B) {
    __shared__ float sIn[8 * 784];
    int b = blockIdx.x;
    int tid = threadIdx.x;
    int ocp = tid / 14, y = tid % 14;
    int oc0 = ocp * 2, oc1 = oc0 + 1;
    float a0[14], a1[14];
    float b0 = __ldg(&B[oc0]), b1 = __ldg(&B[oc1]);
#pragma unroll
    for (int i = 0; i < 14; i++) { a0[i] = b0; a1[i] = b1; }
    const float* in = g_bufA + (size_t)b * 25088;
    for (int tt = 0; tt < 4; tt++) {
        int ic0 = tt * 8;
        __syncthreads();
        for (int i = tid; i < 6272; i += 448) sIn[i] = in[ic0 * 784 + i];
        __syncthreads();
#pragma unroll
        for (int ic = 0; ic < 8; ic++) {
            const float* base = sIn + ic * 784;
            const float* w0 = W + ((size_t)oc0 * 32 + ic0 + ic) * 9;
            const float* w1 = W + ((size_t)oc1 * 32 + ic0 + ic) * 9;
#pragma unroll
            for (int ky = 0; ky < 3; ky++) {
                int iy = 2 * y + ky - 1;
                if (iy < 0 || iy > 27) continue;
                const float* row = base + iy * 28;
                float r[28];
#pragma unroll
                for (int j = 0; j < 28; j++) r[j] = row[j];
#pragma unroll
                for (int kx = 0; kx < 3; kx++) {
                    float wa = __ldg(&w0[ky * 3 + kx]);
                    float wb = __ldg(&w1[ky * 3 + kx]);
#pragma unroll
                    for (int xx = 0; xx < 14; xx++) {
                        int ix = 2 * xx + kx - 1;
                        if (ix >= 0 && ix < 28) {
                            a0[xx] = fmaf(r[ix], wa, a0[xx]);
                            a1[xx] = fmaf(r[ix], wb, a1[xx]);
                        }
                    }
                }
            }
        }
    }
    float* out = g_bufB + (size_t)b * 12544;
#pragma unroll
    for (int xx = 0; xx < 14; xx++) {
        out[oc0 * 196 + y * 14 + xx] = fmaxf(a0[xx], 0.f);
        out[oc1 * 196 + y * 14 + xx] = fmaxf(a1[xx], 0.f);
    }
}

// ===== enc conv3 tiled: 64x14x14 -> 128x7x7 (s2,p1), relu =====
__global__ void __launch_bounds__(448) t_enc3(const float* __restrict__ W,
                                              const float* __restrict__ B) {
    __shared__ float sIn[32 * 196];
    int b = blockIdx.x;
    int tid = threadIdx.x;
    int ocp = tid / 7, y = tid % 7;
    int oc0 = ocp * 2, oc1 = oc0 + 1;
    float a0[7], a1[7];
    float b0 = __ldg(&B[oc0]), b1 = __ldg(&B[oc1]);
#pragma unroll
    for (int i = 0; i < 7; i++) { a0[i] = b0; a1[i] = b1; }
    const float* in = g_bufB + (size_t)b * 12544;
    for (int tt = 0; tt < 2; tt++) {
        int ic0 = tt * 32;
        __syncthreads();
        for (int i = tid; i < 6272; i += 448) sIn[i] = in[ic0 * 196 + i];
        __syncthreads();
#pragma unroll
        for (int ic = 0; ic < 32; ic++) {
            const float* base = sIn + ic * 196;
            const float* w0 = W + ((size_t)oc0 * 64 + ic0 + ic) * 9;
            const float* w1 = W + ((size_t)oc1 * 64 + ic0 + ic) * 9;
#pragma unroll
            for (int ky = 0; ky < 3; ky++) {
                int iy = 2 * y + ky - 1;
                if (iy < 0 || iy > 13) continue;
                const float* row = base + iy * 14;
                float r[14];
#pragma unroll
                for (int j = 0; j < 14; j++) r[j] = row[j];
#pragma unroll
                for (int kx = 0; kx < 3; kx++) {
                    float wa = __ldg(&w0[ky * 3 + kx]);
                    float wb = __ldg(&w1[ky * 3 + kx]);
#pragma unroll
                    for (int xx = 0; xx < 7; xx++) {
                        int ix = 2 * xx + kx - 1;
                        if (ix >= 0 && ix < 14) {
                            a0[xx] = fmaf(r[ix], wa, a0[xx]);
                            a1[xx] = fmaf(r[ix], wb, a1[xx]);
                        }
                    }
                }
            }
        }
    }
    float* out = g_bufC + (size_t)b * 6272;
#pragma unroll
    for (int xx = 0; xx < 7; xx++) {
        out[oc0 * 49 + y * 7 + xx] = fmaxf(a0[xx], 0.f);
        out[oc1 * 49 + y * 7 + xx] = fmaxf(a1[xx], 0.f);
    }
}

// ===== fc stage 1 (split-K): 512 blocks = 128 sample-groups x 4 k-splits =====
// block: 256 thr, 16 samples, j = tid&127 (mu j / lv j-64), rg = tid>>7 -> 8 rows.
// k-split = 1568 = 28 tiles of 56. sA: kk-major [56][16+pad], 4.8KB.
#define FC_PAD 20
__global__ void __launch_bounds__(256) t_fcs(const float* __restrict__ Wmu,
                                             const float* __restrict__ Wlv) {
    __shared__ float sA[56 * FC_PAD];
    int sb = blockIdx.x >> 2;      // sample group [0,128)
    int ks = blockIdx.x & 3;       // k split [0,4)
    int kbase = ks * 1568;
    int tid = threadIdx.x;
    int j  = tid & 127;
    int rg = tid >> 7;
    const float* Wp = (j < 64) ? (Wmu + j) : (Wlv + (j - 64));
    float acc[8];
#pragma unroll
    for (int r = 0; r < 8; r++) acc[r] = 0.f;
    for (int t = 0; t < 28; t++) {
        int k0 = kbase + t * 56;
        __syncthreads();
        for (int i = tid; i < 896; i += 256) {
            int row = i & 15, kk = i >> 4;
            sA[kk * FC_PAD + row] = g_bufC[(size_t)(sb * 16 + row) * 6272 + k0 + kk];
        }
        __syncthreads();
#pragma unroll 14
        for (int kk = 0; kk < 56; kk++) {
            float w = __ldg(&Wp[(size_t)(k0 + kk) * 64]);
            float4 aa = *(const float4*)&sA[kk * FC_PAD + rg * 8];
            float4 ab = *(const float4*)&sA[kk * FC_PAD + rg * 8 + 4];
            acc[0] = fmaf(aa.x, w, acc[0]);
            acc[1] = fmaf(aa.y, w, acc[1]);
            acc[2] = fmaf(aa.z, w, acc[2]);
            acc[3] = fmaf(aa.w, w, acc[3]);
            acc[4] = fmaf(ab.x, w, acc[4]);
            acc[5] = fmaf(ab.y, w, acc[5]);
            acc[6] = fmaf(ab.z, w, acc[6]);
            acc[7] = fmaf(ab.w, w, acc[7]);
        }
    }
#pragma unroll
    for (int r = 0; r < 8; r++) {
        int b = sb * 16 + rg * 8 + r;
        g_part[((size_t)ks * NB + b) * 128 + j] = acc[r];
    }
}

// ===== fc stage 2: reduce 4 partials + bias -> mu/lv + out =====
__global__ void __launch_bounds__(256) t_fcr(const float* __restrict__ bmu,
                                             const float* __restrict__ blv,
                                             float* __restrict__ out) {
    int idx = blockIdx.x * 256 + threadIdx.x;   // [0, 2048*128)
    int j = idx & 127;
    int b = idx >> 7;
    float s = g_part[(size_t)b * 128 + j]
            + g_part[((size_t)NB + b) * 128 + j]
            + g_part[((size_t)2 * NB + b) * 128 + j]
            + g_part[((size_t)3 * NB + b) * 128 + j];
    if (j < 64) {
        s += __ldg(&bmu[j]);
        g_mu[b * 64 + j] = s;
        out[OFF_MU + b * 64 + j] = s;
    } else {
        s += __ldg(&blv[j - 64]);
        g_lv[b * 64 + j - 64] = s;
        out[OFF_LV + b * 64 + j - 64] = s;
    }
}

// ===== reparam + gating + softmax + argmax (verified) =====
__global__ void __launch_bounds__(256) n_gate(const float* __restrict__ eps,
                                              const float* __restrict__ W1, const float* __restrict__ B1,
                                              const float* __restrict__ W2, const float* __restrict__ B2,
                                              const float* __restrict__ W3, const float* __restrict__ B3,
                                              float* __restrict__ out) {
    __shared__ float sW1[4096], sW2[2048], sW3[256], sB1[64], sB2[32], sB3[8];
    int tid = threadIdx.x;
    for (int i = tid; i < 4096; i += 256) sW1[i] = W1[i];
    for (int i = tid; i < 2048; i += 256) sW2[i] = W2[i];
    sW3[tid] = W3[tid];
    if (tid < 64) sB1[tid] = B1[tid];
    if (tid < 32) sB2[tid] = B2[tid];
    if (tid < 8)  sB3[tid] = B3[tid];
    __syncthreads();
    int b = blockIdx.x * 256 + tid;
    float z[64];
#pragma unroll 8
    for (int k = 0; k < 64; k++)
        z[k] = g_mu[b * 64 + k] + __ldg(&eps[b * 64 + k]) * expf(0.5f * g_lv[b * 64 + k]);
    for (int k = 0; k < 64; k++) g_z[b * 64 + k] = z[k];

    float a1[64];
    for (int j = 0; j < 64; j++) {
        float a = sB1[j];
#pragma unroll 8
        for (int k = 0; k < 64; k++) a = fmaf(z[k], sW1[k * 64 + j], a);
        a1[j] = fmaxf(a, 0.f);
    }
    float a2[32];
    for (int j = 0; j < 32; j++) {
        float a = sB2[j];
#pragma unroll 8
        for (int k = 0; k < 64; k++) a = fmaf(a1[k], sW2[k * 32 + j], a);
        a2[j] = fmaxf(a, 0.f);
    }
    float a3[8];
#pragma unroll
    for (int j = 0; j < 8; j++) {
        float a = sB3[j];
#pragma unroll
        for (int k = 0; k < 32; k++) a = fmaf(a2[k], sW3[k * 8 + j], a);
        a3[j] = a;
    }
    float m = a3[0];
#pragma unroll
    for (int e = 1; e < 8; e++) m = fmaxf(m, a3[e]);
    float p[8], s = 0.f;
#pragma unroll
    for (int e = 0; e < 8; e++) { p[e] = expf(a3[e] - m); s += p[e]; }
    float inv = 1.f / s;
    int best = 0; float bv = -1e30f;
#pragma unroll
    for (int e = 0; e < 8; e++) {
        float pe = p[e] * inv;
        out[OFF_PROB + b * 8 + e] = pe;
        out[OFF_LOG + b * 8 + e]  = logf(pe + 1e-8f);
        if (pe > bv) { bv = pe; best = e; }
    }
    g_expert[b] = best;
}

// ===== dec fc (naive, verified): z[64] @ W[e][64,1568] =====
__global__ void __launch_bounds__(256) n_dfc(const float* __restrict__ Wfc,
                                             const float* __restrict__ bfc) {
    int idx = blockIdx.x * 256 + threadIdx.x;
    int j = idx % 1568;
    int b = idx / 1568;
    int e = g_expert[b];
    const float* W = Wfc + (size_t)e * 100352;
    float acc = __ldg(&bfc[(size_t)e * 1568 + j]);
#pragma unroll 8
    for (int k = 0; k < 64; k++)
        acc = fmaf(g_z[b * 64 + k], __ldg(&W[k * 1568 + j]), acc);
    g_bufC[(size_t)b * 1568 + j] = acc;
}

// ===== dec conv1 PHASE-COLLAPSED: up2(32x7x7)->conv3x3 == 2x2 taps on 7x7 =====
__global__ void __launch_bounds__(448) p_dec1(const float* __restrict__ Wall,
                                              const float* __restrict__ ball) {
    __shared__ float sIn[1568];
    int b = blockIdx.x;
    int tid = threadIdx.x;
    int e = g_expert[b];
    const float* in = g_bufC + (size_t)b * 1568;
    for (int i = tid; i < 1568; i += 448) sIn[i] = in[i];
    __syncthreads();
    int ocp = tid / 14, y = tid % 14;
    int oc0 = ocp * 2, oc1 = oc0 + 1;
    int dy = y & 1, i = y >> 1;
    const float* W = Wall + (size_t)e * 18432;
    float a0[14], a1[14];
    float bb0 = __ldg(&ball[e * 64 + oc0]), bb1 = __ldg(&ball[e * 64 + oc1]);
#pragma unroll
    for (int k = 0; k < 14; k++) { a0[k] = bb0; a1[k] = bb1; }
    int r0 = dy ? i : i - 1;
    int r1 = dy ? i + 1 : i;
    bool t0ok = (r0 >= 0);
    bool t1ok = (r1 <= 6);
#pragma unroll 2
    for (int ic = 0; ic < 32; ic++) {
        const float* base = sIn + ic * 49;
        const float* wv0 = W + ((size_t)oc0 * 32 + ic) * 9;
        const float* wv1 = W + ((size_t)oc1 * 32 + ic) * 9;
        float p00 = __ldg(&wv0[0]), p01 = __ldg(&wv0[1]), p02 = __ldg(&wv0[2]);
        float p10 = __ldg(&wv0[3]), p11 = __ldg(&wv0[4]), p12 = __ldg(&wv0[5]);
        float p20 = __ldg(&wv0[6]), p21 = __ldg(&wv0[7]), p22 = __ldg(&wv0[8]);
        float q00 = __ldg(&wv1[0]), q01 = __ldg(&wv1[1]), q02 = __ldg(&wv1[2]);
        float q10 = __ldg(&wv1[3]), q11 = __ldg(&wv1[4]), q12 = __ldg(&wv1[5]);
        float q20 = __ldg(&wv1[6]), q21 = __ldg(&wv1[7]), q22 = __ldg(&wv1[8]);
        float u0p = dy ? (p00 + p10) : p00, u1p = dy ? (p01 + p11) : p01, u2p = dy ? (p02 + p12) : p02;
        float v0p = dy ? p20 : (p10 + p20), v1p = dy ? p21 : (p11 + p21), v2p = dy ? p22 : (p12 + p22);
        float u0q = dy ? (q00 + q10) : q00, u1q = dy ? (q01 + q11) : q01, u2q = dy ? (q02 + q12) : q02;
        float v0q = dy ? q20 : (q10 + q20), v1q = dy ? q21 : (q11 + q21), v2q = dy ? q22 : (q12 + q22);
        if (t0ok) {
            const float* row = base + r0 * 7;
            float r[7];
#pragma unroll
            for (int k = 0; k < 7; k++) r[k] = row[k];
            float Ap = u0p, Bp = u1p + u2p, Cp = u0p + u1p, Dp = u2p;
            float Aq = u0q, Bq = u1q + u2q, Cq = u0q + u1q, Dq = u2q;
#pragma unroll
            for (int jj = 0; jj < 7; jj++) {
                if (jj > 0) { a0[2 * jj] = fmaf(r[jj - 1], Ap, a0[2 * jj]); a1[2 * jj] = fmaf(r[jj - 1], Aq, a1[2 * jj]); }
                a0[2 * jj]     = fmaf(r[jj], Bp, a0[2 * jj]);     a1[2 * jj]     = fmaf(r[jj], Bq, a1[2 * jj]);
                a0[2 * jj + 1] = fmaf(r[jj], Cp, a0[2 * jj + 1]); a1[2 * jj + 1] = fmaf(r[jj], Cq, a1[2 * jj + 1]);
                if (jj < 6) { a0[2 * jj + 1] = fmaf(r[jj + 1], Dp, a0[2 * jj + 1]); a1[2 * jj + 1] = fmaf(r[jj + 1], Dq, a1[2 * jj + 1]); }
            }
        }
        if (t1ok) {
            const float* row = base + r1 * 7;
            float r[7];
#pragma unroll
            for (int k = 0; k < 7; k++) r[k] = row[k];
            float Ap = v0p, Bp = v1p + v2p, Cp = v0p + v1p, Dp = v2p;
            float Aq = v0q, Bq = v1q + v2q, Cq = v0q + v1q, Dq = v2q;
#pragma unroll
            for (int jj = 0; jj < 7; jj++) {
                if (jj > 0) { a0[2 * jj] = fmaf(r[jj - 1], Ap, a0[2 * jj]); a1[2 * jj] = fmaf(r[jj - 1], Aq, a1[2 * jj]); }
                a0[2 * jj]     = fmaf(r[jj], Bp, a0[2 * jj]);     a1[2 * jj]     = fmaf(r[jj], Bq, a1[2 * jj]);
                a0[2 * jj + 1] = fmaf(r[jj], Cp, a0[2 * jj + 1]); a1[2 * jj + 1] = fmaf(r[jj], Cq, a1[2 * jj + 1]);
                if (jj < 6) { a0[2 * jj + 1] = fmaf(r[jj + 1], Dp, a0[2 * jj + 1]); a1[2 * jj + 1] = fmaf(r[jj + 1], Dq, a1[2 * jj + 1]); }
            }
        }
    }
    float* out = g_bufB + (size_t)b * 12544;
#pragma unroll
    for (int xx = 0; xx < 14; xx++) {
        out[oc0 * 196 + y * 14 + xx] = eluf(a0[xx]);
        out[oc1 * 196 + y * 14 + xx] = eluf(a1[xx]);
    }
}

// ===== dec conv2 PHASE-COLLAPSED (reverted, 896 thr, 1 oc/thread) =====
__global__ void __launch_bounds__(896) p_dec2(const float* __restrict__ Wall,
                                              const float* __restrict__ ball) {
    __shared__ float sIn[32 * 196];
    int b = blockIdx.x;
    int tid = threadIdx.x;
    int e = g_expert[b];
    int oc = tid / 28, y = tid % 28;
    int dy = y & 1, i = y >> 1;
    const float* W = Wall + (size_t)e * 18432;
    const float* in = g_bufB + (size_t)b * 12544;
    float acc[28];
    float bi = __ldg(&ball[e * 32 + oc]);
#pragma unroll
    for (int k = 0; k < 28; k++) acc[k] = bi;
    int r0 = dy ? i : i - 1;
    int r1 = dy ? i + 1 : i;
    bool t0ok = (r0 >= 0);
    bool t1ok = (r1 <= 13);
    for (int tt = 0; tt < 2; tt++) {
        int ic0 = tt * 32;
        __syncthreads();
        for (int k = tid; k < 6272; k += 896) sIn[k] = in[ic0 * 196 + k];
        __syncthreads();
#pragma unroll 2
        for (int ic = 0; ic < 32; ic++) {
            const float* base = sIn + ic * 196;
            const float* wv = W + ((size_t)oc * 64 + ic0 + ic) * 9;
            float w00 = __ldg(&wv[0]), w01 = __ldg(&wv[1]), w02 = __ldg(&wv[2]);
            float w10 = __ldg(&wv[3]), w11 = __ldg(&wv[4]), w12 = __ldg(&wv[5]);
            float w20 = __ldg(&wv[6]), w21 = __ldg(&wv[7]), w22 = __ldg(&wv[8]);
            float u0 = dy ? (w00 + w10) : w00;
            float u1 = dy ? (w01 + w11) : w01;
            float u2 = dy ? (w02 + w12) : w02;
            float v0 = dy ? w20 : (w10 + w20);
            float v1 = dy ? w21 : (w11 + w21);
            float v2 = dy ? w22 : (w12 + w22);
            if (t0ok) {
                const float* row = base + r0 * 14;
                float r[14];
#pragma unroll
                for (int k = 0; k < 14; k++) r[k] = row[k];
                float A = u0, B = u1 + u2, C = u0 + u1, D = u2;
#pragma unroll
                for (int jj = 0; jj < 14; jj++) {
                    if (jj > 0) acc[2 * jj] = fmaf(r[jj - 1], A, acc[2 * jj]);
                    acc[2 * jj]     = fmaf(r[jj], B, acc[2 * jj]);
                    acc[2 * jj + 1] = fmaf(r[jj], C, acc[2 * jj + 1]);
                    if (jj < 13) acc[2 * jj + 1] = fmaf(r[jj + 1], D, acc[2 * jj + 1]);
                }
            }
            if (t1ok) {
                const float* row = base + r1 * 14;
                float r[14];
#pragma unroll
                for (int k = 0; k < 14; k++) r[k] = row[k];
                float A = v0, B = v1 + v2, C = v0 + v1, D = v2;
#pragma unroll
                for (int jj = 0; jj < 14; jj++) {
                    if (jj > 0) acc[2 * jj] = fmaf(r[jj - 1], A, acc[2 * jj]);
                    acc[2 * jj]     = fmaf(r[jj], B, acc[2 * jj]);
                    acc[2 * jj + 1] = fmaf(r[jj], C, acc[2 * jj + 1]);
                    if (jj < 13) acc[2 * jj + 1] = fmaf(r[jj + 1], D, acc[2 * jj + 1]);
                }
            }
        }
    }
    float* out = g_bufA + (size_t)b * 25088;
#pragma unroll
    for (int xx = 0; xx < 28; xx++)
        out[oc * 784 + y * 28 + xx] = eluf(acc[xx]);
}

// ===== dec conv3 tiled: 32x28x28 -> 1x28x28, sigmoid -> d_out =====
__global__ void __launch_bounds__(784) t_dec3(const float* __restrict__ Wall,
                                              const float* __restrict__ ball,
                                              float* __restrict__ out) {
    __shared__ float sIn[8 * 784];
    int b = blockIdx.x;
    int tid = threadIdx.x;
    int e = g_expert[b];
    int y = tid / 28, xx = tid % 28;
    const float* W = Wall + (size_t)e * 288;
    const float* in = g_bufA + (size_t)b * 25088;
    float acc = __ldg(&ball[e]);
    for (int tt = 0; tt < 4; tt++) {
        int ic0 = tt * 8;
        __syncthreads();
        for (int i = tid; i < 6272; i += 784) sIn[i] = in[ic0 * 784 + i];
        __syncthreads();
#pragma unroll
        for (int ic = 0; ic < 8; ic++) {
            const float* base = sIn + ic * 784;
            const float* wv = W + (ic0 + ic) * 9;
#pragma unroll
            for (int ky = 0; ky < 3; ky++) {
                int iy = y + ky - 1;
                if (iy < 0 || iy > 27) continue;
#pragma unroll
                for (int kx = 0; kx < 3; kx++) {
                    int ix = xx + kx - 1;
                    if (ix < 0 || ix > 27) continue;
                    acc = fmaf(base[iy * 28 + ix], __ldg(&wv[ky * 3 + kx]), acc);
                }
            }
        }
    }
    out[OFF_REC + b * 784 + tid] = sigmoidf_(acc);
}

// ---------------- launcher ----------------
extern "C" void kernel_launch(void* const* d_in, const int* in_sizes, int n_in,
                              void* d_out, int out_size) {
    // Input-order auto-detection (verified working).
    static const int SZ_INS[26] = {
        1605632, 131072, 288, 32, 18432, 64, 73728, 128,
        401408, 64, 401408, 64, 4096, 64, 2048, 32, 256, 8,
        802816, 12544, 147456, 512, 147456, 256, 2304, 8};
    static const int A[26] = {11, 9, 21, 23, 25, 19, 18, 20, 22, 24, 3, 5, 7,
                              2, 4, 6, 1, 13, 15, 17, 12, 14, 16, 10, 8, 0};
    int perm[26];
    bool ins_ok = (n_in >= 26);
    if (ins_ok) for (int i = 0; i < 26; i++) if (in_sizes[i] != SZ_INS[i]) { ins_ok = false; break; }
    if (ins_ok) {
        for (int i = 0; i < 26; i++) perm[i] = i;
    } else {
        bool alpha_ok = (n_in >= 26);
        if (alpha_ok) for (int k = 0; k < 26; k++) if (in_sizes[k] != SZ_INS[A[k]]) { alpha_ok = false; break; }
        if (alpha_ok) { for (int k = 0; k < 26; k++) perm[A[k]] = k; }
        else          { for (int i = 0; i < 26; i++) perm[i] = i; }
    }
    const float* P[26];
    for (int i = 0; i < 26; i++) P[i] = (const float*)d_in[perm[i]];

    const float* x      = P[0];
    const float* eps    = P[1];
    const float* enc_w1 = P[2];
    const float* enc_b1 = P[3];
    const float* enc_w2 = P[4];
    const float* enc_b2 = P[5];
    const float* enc_w3 = P[6];
    const float* enc_b3 = P[7];
    const float* w_mu   = P[8];
    const float* b_mu   = P[9];
    const float* w_lv   = P[10];
    const float* b_lv   = P[11];
    const float* g_w1   = P[12];
    const float* g_b1   = P[13];
    const float* g_w2   = P[14];
    const float* g_b2   = P[15];
    const float* g_w3   = P[16];
    const float* g_b3   = P[17];
    const float* d_fc_w = P[18];
    const float* d_fc_b = P[19];
    const float* d_w1   = P[20];
    const float* d_b1   = P[21];
    const float* d_w2   = P[22];
    const float* d_b2   = P[23];
    const float* d_w3   = P[24];
    const float* d_b3   = P[25];
    float* out = (float*)d_out;

    t_enc1<<<2048, 256>>>(x, enc_w1, enc_b1);
    t_enc2<<<2048, 448>>>(enc_w2, enc_b2);
    t_enc3<<<2048, 448>>>(enc_w3, enc_b3);
    t_fcs <<<512, 256>>>(w_mu, w_lv);
    t_fcr <<<NB * 128 / 256, 256>>>(b_mu, b_lv, out);
    n_gate<<<2048 / 256, 256>>>(eps, g_w1, g_b1, g_w2, g_b2, g_w3, g_b3, out);
    n_dfc <<<2048 * 1568 / 256, 256>>>(d_fc_w, d_fc_b);
    p_dec1<<<2048, 448>>>(d_w1, d_b1);
    p_dec2<<<2048, 896>>>(d_w2, d_b2);
    t_dec3<<<2048, 784>>>(d_w3, d_b3, out);
}